// round 10
// baseline (speedup 1.0000x reference)
#include <cuda_runtime.h>
#include <cuda_bf16.h>

// Shape (4, 3, 128, 128, 128) fp32.
#define S_SPATIAL   (128 * 128 * 128)              // 2,097,152 per (n,c) segment
#define C_CHAN      3
#define TOTAL_ELEMS (4 * 3 * S_SPATIAL)            // 25,165,824
#define M_PER_CH    (4.0 * (double)S_SPATIAL)      // 8,388,608 per channel

#define THREADS     256
#define NBLK        (148 * 4)                      // 592 blocks = 4 per SM exactly
#define CHUNK_ELEMS 4096                           // channel-uniform (512 chunks/segment)
#define CHUNK_VEC4  (CHUNK_ELEMS / 4)              // 1024 = 4 vec4 per thread
#define N_CHUNKS    (TOTAL_ELEMS / CHUNK_ELEMS)    // 6144

#define LOG2_CLAMP  (-144.26950408889634f)         // -100 / ln(2)
#define LN2         0.6931471805599453

// Per-block, per-channel partials. Every slot rewritten every launch.
__device__ float    g_psum[C_CHAN][NBLK];
__device__ int      g_pcnt[C_CHAN][NBLK];
// Arrival counter: last block resets it -> deterministic graph replays, no init kernel.
__device__ unsigned g_arrive = 0u;

__global__ __launch_bounds__(THREADS, 4) void bce_fused_kernel(
    const float* __restrict__ p_in,
    const float* __restrict__ t_in,
    float* __restrict__ out)
{
    const int tid = threadIdx.x;
    const int b   = blockIdx.x;

    float s0 = 0.0f, s1 = 0.0f, s2 = 0.0f;
    int   c0 = 0,    c1 = 0,    c2 = 0;

    for (int k = b; k < N_CHUNKS; k += NBLK) {
        const int ch = (k >> 9) % C_CHAN;          // chunk-uniform channel
        const float4* __restrict__ p4 = (const float4*)p_in + (size_t)k * CHUNK_VEC4;
        const float4* __restrict__ t4 = (const float4*)t_in + (size_t)k * CHUNK_VEC4;

        // Front-batched loads: 8 independent LDG.128 in flight (MLP=8).
        float4 pv[4], tv[4];
        #pragma unroll
        for (int u = 0; u < 4; u++) pv[u] = __ldcs(&p4[tid + u * THREADS]);
        #pragma unroll
        for (int u = 0; u < 4; u++) tv[u] = __ldcs(&t4[tid + u * THREADS]);

        float csum = 0.0f;
        int   ccnt = 0;
        #pragma unroll
        for (int u = 0; u < 4; u++) {
            {
                bool one = (tv[u].x != 0.0f);
                float x = one ? pv[u].x : (1.0f - pv[u].x);
                csum += fmaxf(__log2f(x), LOG2_CLAMP);
                ccnt += one;
            }
            {
                bool one = (tv[u].y != 0.0f);
                float x = one ? pv[u].y : (1.0f - pv[u].y);
                csum += fmaxf(__log2f(x), LOG2_CLAMP);
                ccnt += one;
            }
            {
                bool one = (tv[u].z != 0.0f);
                float x = one ? pv[u].z : (1.0f - pv[u].z);
                csum += fmaxf(__log2f(x), LOG2_CLAMP);
                ccnt += one;
            }
            {
                bool one = (tv[u].w != 0.0f);
                float x = one ? pv[u].w : (1.0f - pv[u].w);
                csum += fmaxf(__log2f(x), LOG2_CLAMP);
                ccnt += one;
            }
        }

        // Route chunk partial into the channel accumulator (uniform branch).
        if (ch == 0)      { s0 += csum; c0 += ccnt; }
        else if (ch == 1) { s1 += csum; c1 += ccnt; }
        else              { s2 += csum; c2 += ccnt; }
    }

    // ---- Block reduction (3 channels) ----
    const int wid = tid >> 5;
    const int lid = tid & 31;
    #pragma unroll
    for (int off = 16; off > 0; off >>= 1) {
        s0 += __shfl_xor_sync(0xFFFFFFFFu, s0, off);
        s1 += __shfl_xor_sync(0xFFFFFFFFu, s1, off);
        s2 += __shfl_xor_sync(0xFFFFFFFFu, s2, off);
        c0 += __shfl_xor_sync(0xFFFFFFFFu, c0, off);
        c1 += __shfl_xor_sync(0xFFFFFFFFu, c1, off);
        c2 += __shfl_xor_sync(0xFFFFFFFFu, c2, off);
    }

    __shared__ float sh_s[C_CHAN][THREADS / 32];
    __shared__ int   sh_c[C_CHAN][THREADS / 32];
    __shared__ bool  sh_last;
    if (lid == 0) {
        sh_s[0][wid] = s0; sh_s[1][wid] = s1; sh_s[2][wid] = s2;
        sh_c[0][wid] = c0; sh_c[1][wid] = c1; sh_c[2][wid] = c2;
    }
    __syncthreads();

    if (tid == 0) {
        float bs0 = 0.f, bs1 = 0.f, bs2 = 0.f;
        int   bc0 = 0,   bc1 = 0,   bc2 = 0;
        #pragma unroll
        for (int w = 0; w < THREADS / 32; w++) {
            bs0 += sh_s[0][w]; bs1 += sh_s[1][w]; bs2 += sh_s[2][w];
            bc0 += sh_c[0][w]; bc1 += sh_c[1][w]; bc2 += sh_c[2][w];
        }
        g_psum[0][b] = bs0; g_psum[1][b] = bs1; g_psum[2][b] = bs2;
        g_pcnt[0][b] = bc0; g_pcnt[1][b] = bc1; g_pcnt[2][b] = bc2;
        __threadfence();
        unsigned prev = atomicAdd(&g_arrive, 1u);
        sh_last = (prev == NBLK - 1);
    }
    __syncthreads();

    if (!sh_last) return;

    // ---- Last block: reduce NBLK partials per channel ----
    double    ds0 = 0.0, ds1 = 0.0, ds2 = 0.0;
    long long dc0 = 0,   dc1 = 0,   dc2 = 0;
    for (int s = tid; s < NBLK; s += THREADS) {
        ds0 += (double)g_psum[0][s]; dc0 += g_pcnt[0][s];
        ds1 += (double)g_psum[1][s]; dc1 += g_pcnt[1][s];
        ds2 += (double)g_psum[2][s]; dc2 += g_pcnt[2][s];
    }
    #pragma unroll
    for (int off = 16; off > 0; off >>= 1) {
        ds0 += __shfl_xor_sync(0xFFFFFFFFu, ds0, off);
        ds1 += __shfl_xor_sync(0xFFFFFFFFu, ds1, off);
        ds2 += __shfl_xor_sync(0xFFFFFFFFu, ds2, off);
        dc0 += __shfl_xor_sync(0xFFFFFFFFu, dc0, off);
        dc1 += __shfl_xor_sync(0xFFFFFFFFu, dc1, off);
        dc2 += __shfl_xor_sync(0xFFFFFFFFu, dc2, off);
    }

    __shared__ double    fd_s[C_CHAN][THREADS / 32];
    __shared__ long long fd_c[C_CHAN][THREADS / 32];
    if (lid == 0) {
        fd_s[0][wid] = ds0; fd_s[1][wid] = ds1; fd_s[2][wid] = ds2;
        fd_c[0][wid] = dc0; fd_c[1][wid] = dc1; fd_c[2][wid] = dc2;
    }
    __syncthreads();

    if (tid == 0) {
        double total = 0.0;
        #pragma unroll
        for (int ch = 0; ch < C_CHAN; ch++) {
            double s = 0.0;
            long long ones = 0;
            #pragma unroll
            for (int w = 0; w < THREADS / 32; w++) {
                s    += fd_s[ch][w];
                ones += fd_c[ch][w];
            }
            double bce = -(s * LN2) / M_PER_CH;       // log2-sum -> natural-log mean
            double wgt = (ones > 0) ? (M_PER_CH / (double)ones)
                                    : 1000.0;          // EMPTY_WEIGHT
            total += wgt * bce;
        }
        out[0] = (float)(total / (double)C_CHAN);
        g_arrive = 0u;                                 // self-reset for next replay
    }
}

extern "C" void kernel_launch(void* const* d_in, const int* in_sizes, int n_in,
                              void* d_out, int out_size) {
    const float* input  = (const float*)d_in[0];
    const float* target = (const float*)d_in[1];
    float* out = (float*)d_out;

    bce_fused_kernel<<<NBLK, THREADS>>>(input, target, out);
}

// round 11
// speedup vs baseline: 1.0390x; 1.0390x over previous
#include <cuda_runtime.h>
#include <cuda_bf16.h>

// Problem constants: input shape (N=4, C=3, 128,128,128), fp32.
#define S_SPATIAL (128 * 128 * 128)          // 2,097,152 contiguous elems per (n,c) segment
#define N_BATCH   4
#define C_CHAN    3
#define N_SEG     (N_BATCH * C_CHAN)          // 12 contiguous segments
#define M_PER_CH  ((long long)N_BATCH * S_SPATIAL)   // 8,388,608 elems per channel

#define BLOCKS_PER_SEG 64
#define THREADS        256
#define SLOTS_PER_CH   (N_BATCH * BLOCKS_PER_SEG)    // 256 partial slots per channel
#define TOTAL_BLOCKS   (N_SEG * BLOCKS_PER_SEG)      // 768
#define ELEMS_PER_BLK  (S_SPATIAL / BLOCKS_PER_SEG)  // 32768
#define VEC4_PER_BLK   (ELEMS_PER_BLK / 4)           // 8192

// Per-block partials, channel-major: slot = c * 256 + (n * 64 + chunk).
// Every slot is overwritten on every launch -> no init kernel, no atomics,
// deterministic across graph replays. Kernel boundary orders writes for the
// final kernel (no fences needed).
__device__ float g_psum[C_CHAN * SLOTS_PER_CH];
__device__ int   g_pcnt[C_CHAN * SLOTS_PER_CH];

// ---- Kernel 1: streaming BCE partial reduction (round-8 mainloop, verbatim) ----
__global__ __launch_bounds__(THREADS) void bce_reduce_kernel(
    const float* __restrict__ p_in,
    const float* __restrict__ t_in)
{
    const int seg   = blockIdx.x >> 6;        // blockIdx.x / 64
    const int chunk = blockIdx.x & 63;
    const int c     = seg % C_CHAN;           // channel is uniform per block
    const int n     = seg / C_CHAN;           // batch index

    const size_t base = (size_t)seg * S_SPATIAL + (size_t)chunk * ELEMS_PER_BLK;
    const float4* __restrict__ p4 = (const float4*)(p_in + base);
    const float4* __restrict__ t4 = (const float4*)(t_in + base);

    float sum = 0.0f;
    int   cnt = 0;

    #pragma unroll 4
    for (int i = threadIdx.x; i < VEC4_PER_BLK; i += THREADS) {
        float4 pv = p4[i];
        float4 tv = t4[i];

        {
            bool one = (tv.x != 0.0f);
            float x = one ? pv.x : (1.0f - pv.x);
            sum += fmaxf(__logf(x), -100.0f);
            cnt += one;
        }
        {
            bool one = (tv.y != 0.0f);
            float x = one ? pv.y : (1.0f - pv.y);
            sum += fmaxf(__logf(x), -100.0f);
            cnt += one;
        }
        {
            bool one = (tv.z != 0.0f);
            float x = one ? pv.z : (1.0f - pv.z);
            sum += fmaxf(__logf(x), -100.0f);
            cnt += one;
        }
        {
            bool one = (tv.w != 0.0f);
            float x = one ? pv.w : (1.0f - pv.w);
            sum += fmaxf(__logf(x), -100.0f);
            cnt += one;
        }
    }

    // Warp reduction
    #pragma unroll
    for (int off = 16; off > 0; off >>= 1) {
        sum += __shfl_xor_sync(0xFFFFFFFFu, sum, off);
        cnt += __shfl_xor_sync(0xFFFFFFFFu, cnt, off);
    }

    // Block reduction across 8 warps
    __shared__ float s_sum[THREADS / 32];
    __shared__ int   s_cnt[THREADS / 32];
    const int wid = threadIdx.x >> 5;
    const int lid = threadIdx.x & 31;
    if (lid == 0) {
        s_sum[wid] = sum;
        s_cnt[wid] = cnt;
    }
    __syncthreads();

    if (threadIdx.x == 0) {
        float bsum = 0.0f;
        int   bcnt = 0;
        #pragma unroll
        for (int w = 0; w < THREADS / 32; w++) {
            bsum += s_sum[w];
            bcnt += s_cnt[w];
        }
        const int slot = c * SLOTS_PER_CH + n * BLOCKS_PER_SEG + chunk;
        g_psum[slot] = bsum;      // plain store; no init, no atomics
        g_pcnt[slot] = bcnt;
    }
}

// ---- Kernel 2: reduce 768 partials (3 channels x 256 slots) and finalize ----
__global__ __launch_bounds__(THREADS) void bce_final_kernel(float* __restrict__ out)
{
    const int tid = threadIdx.x;              // 0..255, one slot per channel
    const int wid = tid >> 5;
    const int lid = tid & 31;

    double ds0 = (double)g_psum[0 * SLOTS_PER_CH + tid];
    double ds1 = (double)g_psum[1 * SLOTS_PER_CH + tid];
    double ds2 = (double)g_psum[2 * SLOTS_PER_CH + tid];
    int    dc0 = g_pcnt[0 * SLOTS_PER_CH + tid];
    int    dc1 = g_pcnt[1 * SLOTS_PER_CH + tid];
    int    dc2 = g_pcnt[2 * SLOTS_PER_CH + tid];

    #pragma unroll
    for (int off = 16; off > 0; off >>= 1) {
        ds0 += __shfl_xor_sync(0xFFFFFFFFu, ds0, off);
        ds1 += __shfl_xor_sync(0xFFFFFFFFu, ds1, off);
        ds2 += __shfl_xor_sync(0xFFFFFFFFu, ds2, off);
        dc0 += __shfl_xor_sync(0xFFFFFFFFu, dc0, off);
        dc1 += __shfl_xor_sync(0xFFFFFFFFu, dc1, off);
        dc2 += __shfl_xor_sync(0xFFFFFFFFu, dc2, off);
    }

    __shared__ double f_sum[C_CHAN][THREADS / 32];
    __shared__ int    f_cnt[C_CHAN][THREADS / 32];
    if (lid == 0) {
        f_sum[0][wid] = ds0; f_sum[1][wid] = ds1; f_sum[2][wid] = ds2;
        f_cnt[0][wid] = dc0; f_cnt[1][wid] = dc1; f_cnt[2][wid] = dc2;
    }
    __syncthreads();

    if (tid == 0) {
        double total = 0.0;
        #pragma unroll
        for (int ch = 0; ch < C_CHAN; ch++) {
            double s = 0.0;
            long long ones = 0;
            #pragma unroll
            for (int w = 0; w < THREADS / 32; w++) {
                s    += f_sum[ch][w];
                ones += f_cnt[ch][w];
            }
            double bce = -s / (double)M_PER_CH;                 // channel mean, negated
            double wgt = (ones > 0) ? ((double)M_PER_CH / (double)ones)
                                    : 1000.0;                   // EMPTY_WEIGHT
            total += wgt * bce;
        }
        out[0] = (float)(total / (double)C_CHAN);
    }
}

extern "C" void kernel_launch(void* const* d_in, const int* in_sizes, int n_in,
                              void* d_out, int out_size) {
    const float* input  = (const float*)d_in[0];
    const float* target = (const float*)d_in[1];
    float* out = (float*)d_out;

    bce_reduce_kernel<<<TOTAL_BLOCKS, THREADS>>>(input, target);
    bce_final_kernel<<<1, THREADS>>>(out);
}

// round 12
// speedup vs baseline: 1.0959x; 1.0548x over previous
#include <cuda_runtime.h>
#include <cuda_bf16.h>

// Problem constants: input shape (N=4, C=3, 128,128,128), fp32.
#define S_SPATIAL (128 * 128 * 128)          // 2,097,152 contiguous elems per (n,c) segment
#define N_BATCH   4
#define C_CHAN    3
#define N_SEG     (N_BATCH * C_CHAN)          // 12 contiguous segments
#define M_PER_CH  ((long long)N_BATCH * S_SPATIAL)   // 8,388,608 elems per channel

#define BLOCKS_PER_SEG 64
#define THREADS        256
#define SLOTS_PER_CH   (N_BATCH * BLOCKS_PER_SEG)    // 256 partial slots per channel
#define TOTAL_BLOCKS   (N_SEG * BLOCKS_PER_SEG)      // 768
#define ELEMS_PER_BLK  (S_SPATIAL / BLOCKS_PER_SEG)  // 32768
#define VEC4_PER_BLK   (ELEMS_PER_BLK / 4)           // 8192

// Per-block partials, channel-major: slot = c * 256 + (n * 64 + chunk).
// Every slot is overwritten on every launch -> no init pass required.
__device__ float    g_psum[C_CHAN * SLOTS_PER_CH];
__device__ int      g_pcnt[C_CHAN * SLOTS_PER_CH];
// Arrival counter: last block resets it to 0 -> deterministic graph replays
// with no init kernel.
__device__ unsigned g_arrive = 0u;

__global__ __launch_bounds__(THREADS) void bce_fused_kernel(
    const float* __restrict__ p_in,
    const float* __restrict__ t_in,
    float* __restrict__ out)
{
    const int seg   = blockIdx.x >> 6;        // 0..11
    const int chunk = blockIdx.x & 63;
    const int c     = seg % C_CHAN;           // channel, uniform per block
    const int n     = seg / C_CHAN;           // batch index

    const size_t base = (size_t)seg * S_SPATIAL + (size_t)chunk * ELEMS_PER_BLK;
    const float4* __restrict__ p4 = (const float4*)(p_in + base);
    const float4* __restrict__ t4 = (const float4*)(t_in + base);

    float sum = 0.0f;
    int   cnt = 0;

    // Round-8 mainloop, verbatim (measured ~31.8us / ~79-84% DRAM).
    #pragma unroll 4
    for (int i = threadIdx.x; i < VEC4_PER_BLK; i += THREADS) {
        float4 pv = p4[i];
        float4 tv = t4[i];
        {
            bool one = (tv.x != 0.0f);
            float x = one ? pv.x : (1.0f - pv.x);
            sum += fmaxf(__logf(x), -100.0f);
            cnt += one;
        }
        {
            bool one = (tv.y != 0.0f);
            float x = one ? pv.y : (1.0f - pv.y);
            sum += fmaxf(__logf(x), -100.0f);
            cnt += one;
        }
        {
            bool one = (tv.z != 0.0f);
            float x = one ? pv.z : (1.0f - pv.z);
            sum += fmaxf(__logf(x), -100.0f);
            cnt += one;
        }
        {
            bool one = (tv.w != 0.0f);
            float x = one ? pv.w : (1.0f - pv.w);
            sum += fmaxf(__logf(x), -100.0f);
            cnt += one;
        }
    }

    // Warp reduction
    #pragma unroll
    for (int off = 16; off > 0; off >>= 1) {
        sum += __shfl_xor_sync(0xFFFFFFFFu, sum, off);
        cnt += __shfl_xor_sync(0xFFFFFFFFu, cnt, off);
    }

    // Block reduction across 8 warps
    __shared__ float s_sum[THREADS / 32];
    __shared__ int   s_cnt[THREADS / 32];
    __shared__ bool  s_last;
    const int wid = threadIdx.x >> 5;
    const int lid = threadIdx.x & 31;
    if (lid == 0) {
        s_sum[wid] = sum;
        s_cnt[wid] = cnt;
    }
    __syncthreads();

    if (threadIdx.x == 0) {
        float bsum = 0.0f;
        int   bcnt = 0;
        #pragma unroll
        for (int w = 0; w < THREADS / 32; w++) {
            bsum += s_sum[w];
            bcnt += s_cnt[w];
        }
        const int slot = c * SLOTS_PER_CH + n * BLOCKS_PER_SEG + chunk;
        g_psum[slot] = bsum;
        g_pcnt[slot] = bcnt;
        __threadfence();                         // publish partials device-wide
        unsigned prev = atomicAdd(&g_arrive, 1u);
        s_last = (prev == TOTAL_BLOCKS - 1);
    }
    __syncthreads();

    if (!s_last) return;

    // ---- Last block: cheap fp32/int tail (no double shuffles) ----
    // 3 channels x 256 slots; thread tid owns one slot per channel.
    // fp32 pairwise tree over 256 block-partials: rel error ~5e-7, far inside 1e-3.
    const int tid = threadIdx.x;
    float fs0 = g_psum[0 * SLOTS_PER_CH + tid];
    float fs1 = g_psum[1 * SLOTS_PER_CH + tid];
    float fs2 = g_psum[2 * SLOTS_PER_CH + tid];
    int   ic0 = g_pcnt[0 * SLOTS_PER_CH + tid];
    int   ic1 = g_pcnt[1 * SLOTS_PER_CH + tid];
    int   ic2 = g_pcnt[2 * SLOTS_PER_CH + tid];

    #pragma unroll
    for (int off = 16; off > 0; off >>= 1) {
        fs0 += __shfl_xor_sync(0xFFFFFFFFu, fs0, off);
        fs1 += __shfl_xor_sync(0xFFFFFFFFu, fs1, off);
        fs2 += __shfl_xor_sync(0xFFFFFFFFu, fs2, off);
        ic0 += __shfl_xor_sync(0xFFFFFFFFu, ic0, off);
        ic1 += __shfl_xor_sync(0xFFFFFFFFu, ic1, off);
        ic2 += __shfl_xor_sync(0xFFFFFFFFu, ic2, off);
    }

    __shared__ float f_sum[C_CHAN][THREADS / 32];
    __shared__ int   f_cnt[C_CHAN][THREADS / 32];
    if (lid == 0) {
        f_sum[0][wid] = fs0; f_sum[1][wid] = fs1; f_sum[2][wid] = fs2;
        f_cnt[0][wid] = ic0; f_cnt[1][wid] = ic1; f_cnt[2][wid] = ic2;
    }
    __syncthreads();

    if (tid == 0) {
        double total = 0.0;
        #pragma unroll
        for (int ch = 0; ch < C_CHAN; ch++) {
            float s = 0.0f;
            int   ones = 0;
            #pragma unroll
            for (int w = 0; w < THREADS / 32; w++) {
                s    += f_sum[ch][w];
                ones += f_cnt[ch][w];
            }
            double bce = -(double)s / (double)M_PER_CH;        // channel mean, negated
            double wgt = (ones > 0) ? ((double)M_PER_CH / (double)ones)
                                    : 1000.0;                  // EMPTY_WEIGHT
            total += wgt * bce;
        }
        out[0] = (float)(total / (double)C_CHAN);
        g_arrive = 0u;                                         // self-reset for next replay
    }
}

extern "C" void kernel_launch(void* const* d_in, const int* in_sizes, int n_in,
                              void* d_out, int out_size) {
    const float* input  = (const float*)d_in[0];
    const float* target = (const float*)d_in[1];
    float* out = (float*)d_out;

    bce_fused_kernel<<<TOTAL_BLOCKS, THREADS>>>(input, target, out);
}